// round 4
// baseline (speedup 1.0000x reference)
#include <cuda_runtime.h>
#include <math_constants.h>

// loss over three persistence diagrams, each (8M, 2) f32.
//   l = dgm[:,0] - dgm[:,1], nonfinite -> 0
//   top1 = max(l0); t01 = 1 - top1^2; t0 = sum(l0^2) - top1^2
//   t1 = sum(l1^2); t2 = sum(l2^2); loss = t01+t0+t1+t2
// Single fused kernel: simple grid-stride loop (R2's 6.2 TB/s form),
// per-block partials, last-block-done finalize.

#define BPA 512            // blocks per array
#define THREADS 256
#define NBLOCKS (3 * BPA)

__device__ float g_part_sum[3 * BPA];
__device__ float g_part_max[BPA];
__device__ unsigned int g_done = 0;

__global__ __launch_bounds__(THREADS) void toploss_fused(
    const float4* __restrict__ d0,
    const float4* __restrict__ d1,
    const float4* __restrict__ d2,
    float* __restrict__ out,
    int n4)
{
    const int arr = blockIdx.x / BPA;
    const int b   = blockIdx.x % BPA;
    const int tid = threadIdx.x;
    const float4* __restrict__ p = (arr == 0) ? d0 : ((arr == 1) ? d1 : d2);

    const int stride = BPA * THREADS;

    float sum = 0.0f;
    float mx  = -CUDART_INF_F;

    #pragma unroll 4
    for (int i = b * THREADS + tid; i < n4; i += stride) {
        float4 v = p[i];
        float la = v.x - v.y;
        float lb = v.z - v.w;
        if (!isfinite(la)) la = 0.0f;
        if (!isfinite(lb)) lb = 0.0f;
        mx  = fmaxf(mx, fmaxf(la, lb));
        sum = fmaf(la, la, sum);
        sum = fmaf(lb, lb, sum);
    }

    // ---- block reduction ----
    __shared__ float ssum[THREADS];
    __shared__ float smax[THREADS];
    ssum[tid] = sum;
    smax[tid] = mx;
    __syncthreads();
    #pragma unroll
    for (int off = THREADS / 2; off >= 32; off >>= 1) {
        if (tid < off) {
            ssum[tid] += ssum[tid + off];
            smax[tid]  = fmaxf(smax[tid], smax[tid + off]);
        }
        __syncthreads();
    }
    if (tid < 32) {
        float s = ssum[tid];
        float m = smax[tid];
        #pragma unroll
        for (int off = 16; off > 0; off >>= 1) {
            s += __shfl_down_sync(0xFFFFFFFFu, s, off);
            m  = fmaxf(m, __shfl_down_sync(0xFFFFFFFFu, m, off));
        }
        if (tid == 0) {
            g_part_sum[arr * BPA + b] = s;
            if (arr == 0) g_part_max[b] = m;
        }
    }

    // ---- last-block-done finalize ----
    __shared__ bool s_last;
    __syncthreads();
    if (tid == 0) {
        __threadfence();
        unsigned int prev = atomicAdd(&g_done, 1u);
        s_last = (prev == NBLOCKS - 1);
    }
    __syncthreads();
    if (!s_last) return;

    float a0 = 0.0f, a1 = 0.0f, a2 = 0.0f;
    float fm = -CUDART_INF_F;
    #pragma unroll
    for (int k = tid; k < BPA; k += THREADS) {
        a0 += g_part_sum[0 * BPA + k];
        a1 += g_part_sum[1 * BPA + k];
        a2 += g_part_sum[2 * BPA + k];
        fm  = fmaxf(fm, g_part_max[k]);
    }

    __shared__ float sh0[THREADS], sh1[THREADS], sh2[THREADS], shm[THREADS];
    sh0[tid] = a0; sh1[tid] = a1; sh2[tid] = a2; shm[tid] = fm;
    __syncthreads();
    #pragma unroll
    for (int off = THREADS / 2; off >= 32; off >>= 1) {
        if (tid < off) {
            sh0[tid] += sh0[tid + off];
            sh1[tid] += sh1[tid + off];
            sh2[tid] += sh2[tid + off];
            shm[tid]  = fmaxf(shm[tid], shm[tid + off]);
        }
        __syncthreads();
    }
    if (tid < 32) {
        float x = sh0[tid], y = sh1[tid], z = sh2[tid], mm = shm[tid];
        #pragma unroll
        for (int off = 16; off > 0; off >>= 1) {
            x += __shfl_down_sync(0xFFFFFFFFu, x, off);
            y += __shfl_down_sync(0xFFFFFFFFu, y, off);
            z += __shfl_down_sync(0xFFFFFFFFu, z, off);
            mm = fmaxf(mm, __shfl_down_sync(0xFFFFFFFFu, mm, off));
        }
        if (tid == 0) {
            float top1 = mm;
            float t01  = 1.0f - top1 * top1;
            float t0   = x - top1 * top1;
            float loss = t01 + t0 + y + z;
            out[0] = loss;
            out[1] = t01;
            out[2] = t0;
            out[3] = y;
            out[4] = z;
            g_done = 0;   // reset for next graph replay
        }
    }
}

extern "C" void kernel_launch(void* const* d_in, const int* in_sizes, int n_in,
                              void* d_out, int out_size)
{
    const float4* d0 = (const float4*)d_in[0];
    const float4* d1 = (const float4*)d_in[1];
    const float4* d2 = (const float4*)d_in[2];
    float* out = (float*)d_out;

    const int n4 = in_sizes[0] / 4;   // float4s per array (2 bars each)

    toploss_fused<<<NBLOCKS, THREADS>>>(d0, d1, d2, out, n4);
}